// round 3
// baseline (speedup 1.0000x reference)
#include <cuda_runtime.h>

// SineRnn: persistent 2-layer LSTM, B=256, T=512, predict=32, H=512.
// 128 CTAs x 256 threads. Column-partitioned (4 units/CTA), weights in SMEM,
// h exchanged via device-global double buffers + grid barrier, FFMA2 compute.

#define Hn    512
#define Bn    256
#define Tn    512
#define Pn    32
#define TPn   544
#define NCTA  128
#define NTHR  256
#define K2n   256   // H/2 k-pairs
#define CHn   16    // k2 per staged chunk
#define NCHUNK 16
#define ZP    260   // zbuf padded stride

__device__ float2   g_h1[2][K2n * Bn];
__device__ float2   g_h2[2][K2n * Bn];
__device__ float    g_out[TPn * Bn];
__device__ unsigned g_cnt;
__device__ unsigned g_gen;

struct Smem {
  float2 wh1[K2n * 16];     // 32 KB  [k2][gc] gate-col pairs (k even, k odd)
  float2 wx2[K2n * 16];     // 32 KB
  float2 wh2[K2n * 16];     // 32 KB
  float2 hs[2][CHn * Bn];   // 64 KB  double-buffered h staging [k2l][b]
  float  zbuf[16 * ZP];     // padded z exchange
  float  c1[4 * Bn];
  float  c2[4 * Bn];
  float  wx1[16];
  float  bias1[16];
  float  bias2[16];
  float  wl[4];
  float  red[8];
};

__device__ __forceinline__ float2 ffma2(float2 a, float2 b, float2 c) {
  unsigned long long au = *reinterpret_cast<unsigned long long*>(&a);
  unsigned long long bu = *reinterpret_cast<unsigned long long*>(&b);
  unsigned long long cu = *reinterpret_cast<unsigned long long*>(&c);
  unsigned long long du;
  asm("fma.rn.f32x2 %0, %1, %2, %3;" : "=l"(du) : "l"(au), "l"(bu), "l"(cu));
  return *reinterpret_cast<float2*>(&du);
}

__device__ __forceinline__ void cp_async16(void* sdst, const void* gsrc) {
  unsigned sa = (unsigned)__cvta_generic_to_shared(sdst);
  asm volatile("cp.async.cg.shared.global [%0], [%1], 16;\n" :: "r"(sa), "l"(gsrc));
}
__device__ __forceinline__ void cp_commit() { asm volatile("cp.async.commit_group;\n"); }
__device__ __forceinline__ void cp_wait1()  { asm volatile("cp.async.wait_group 1;\n"); }
__device__ __forceinline__ void cp_wait0()  { asm volatile("cp.async.wait_group 0;\n"); }

__device__ __forceinline__ float sigf(float x) { return 1.f / (1.f + expf(-x)); }

__device__ __forceinline__ void grid_barrier() {
  __threadfence();
  __syncthreads();
  if (threadIdx.x == 0) {
    volatile unsigned* vgen = &g_gen;
    unsigned gen = *vgen;
    __threadfence();
    unsigned ticket = atomicAdd(&g_cnt, 1u);
    if (ticket == (unsigned)gridDim.x - 1u) {
      g_cnt = 0u;
      __threadfence();
      *vgen = gen + 1u;
    } else {
      while (*vgen == gen) { __nanosleep(64); }
    }
    __threadfence();
  }
  __syncthreads();
}

__device__ __forceinline__ void stage_chunk(float4* dst, const float4* src, int tid) {
#pragma unroll
  for (int i = 0; i < 8; ++i)
    cp_async16(dst + i * NTHR + tid, src + i * NTHR + tid);
  cp_commit();
}

// Accumulate one full h-matrix pass. DUAL: za += h@Wa and zb += h@Wb.
template <bool DUAL>
__device__ __forceinline__ void mat_pass(
    Smem* s, const float2* __restrict__ gsrc,
    const float2* __restrict__ wsA, const float2* __restrict__ wsB,
    float2 (&za)[8][2], float2 (&zb)[8][2],
    int tid, int bg, int gcp)
{
  const float4* src4 = reinterpret_cast<const float4*>(gsrc);
  float4* hb0 = reinterpret_cast<float4*>(s->hs[0]);
  float4* hb1 = reinterpret_cast<float4*>(s->hs[1]);
  stage_chunk(hb0, src4, tid);
  for (int c = 0; c < NCHUNK; ++c) {
    float4* cur = (c & 1) ? hb1 : hb0;
    if (c + 1 < NCHUNK) {
      stage_chunk((c & 1) ? hb0 : hb1, src4 + (c + 1) * (CHn * Bn / 2), tid);
      cp_wait1();
    } else {
      cp_wait0();
    }
    __syncthreads();
    const float4* wA = reinterpret_cast<const float4*>(wsA) + (c * CHn) * 8 + gcp;
    const float4* wB = reinterpret_cast<const float4*>(wsB) + (c * CHn) * 8 + gcp;
    const float4* hp = cur + bg * 4;
#pragma unroll 4
    for (int k2l = 0; k2l < CHn; ++k2l) {
      float4 hv[4];
#pragma unroll
      for (int i = 0; i < 4; ++i) hv[i] = hp[k2l * (Bn / 2) + i];
      float4 A = wA[k2l * 8];
      float2 a0 = make_float2(A.x, A.y);
      float2 a1 = make_float2(A.z, A.w);
      float2 b0v, b1v;
      if (DUAL) {
        float4 Bv = wB[k2l * 8];
        b0v = make_float2(Bv.x, Bv.y);
        b1v = make_float2(Bv.z, Bv.w);
      }
#pragma unroll
      for (int i = 0; i < 4; ++i) {
        float2 hlo = make_float2(hv[i].x, hv[i].y);   // batch 2i
        float2 hhi = make_float2(hv[i].z, hv[i].w);   // batch 2i+1
        za[2 * i + 0][0] = ffma2(hlo, a0, za[2 * i + 0][0]);
        za[2 * i + 0][1] = ffma2(hlo, a1, za[2 * i + 0][1]);
        za[2 * i + 1][0] = ffma2(hhi, a0, za[2 * i + 1][0]);
        za[2 * i + 1][1] = ffma2(hhi, a1, za[2 * i + 1][1]);
        if (DUAL) {
          zb[2 * i + 0][0] = ffma2(hlo, b0v, zb[2 * i + 0][0]);
          zb[2 * i + 0][1] = ffma2(hlo, b1v, zb[2 * i + 0][1]);
          zb[2 * i + 1][0] = ffma2(hhi, b0v, zb[2 * i + 1][0]);
          zb[2 * i + 1][1] = ffma2(hhi, b1v, zb[2 * i + 1][1]);
        }
      }
    }
    __syncthreads();
  }
}

__global__ void __launch_bounds__(NTHR, 1) sine_rnn_kernel(
    const float* __restrict__ seq,
    const float* __restrict__ Wx1, const float* __restrict__ bx1,
    const float* __restrict__ Wh1, const float* __restrict__ bh1,
    const float* __restrict__ Wx2, const float* __restrict__ bx2,
    const float* __restrict__ Wh2, const float* __restrict__ bh2,
    const float* __restrict__ Wl,  const float* __restrict__ bl,
    float* __restrict__ out)
{
  extern __shared__ char smem_raw[];
  Smem* s = reinterpret_cast<Smem*>(smem_raw);

  const int tid  = threadIdx.x;
  const int lane = tid & 31;
  const int warp = tid >> 5;
  const int gcp  = lane & 7;            // gate-col pair index (gc = 2*gcp, 2*gcp+1)
  const int bg   = warp * 4 + (lane >> 3);  // batch octet index 0..31
  const int b0   = bg * 8;
  const int cta  = blockIdx.x;
  const int u0   = cta * 4;
  const float bl0 = bl[0];

  // ---------------- one-time init ----------------
  // Weight slices into SMEM: gc = gate*4 + unit; element pair (k even, k odd)
  {
    float* wh1f = reinterpret_cast<float*>(s->wh1);
    float* wx2f = reinterpret_cast<float*>(s->wx2);
    float* wh2f = reinterpret_cast<float*>(s->wh2);
    for (int idx = tid; idx < Hn * 16; idx += NTHR) {
      int k = idx >> 4, gc = idx & 15;
      int col = u0 + (gc & 3) + ((gc >> 2) << 9);
      int dst = ((k >> 1) * 16 + gc) * 2 + (k & 1);
      wh1f[dst] = Wh1[k * 2048 + col];
      wx2f[dst] = Wx2[k * 2048 + col];
      wh2f[dst] = Wh2[k * 2048 + col];
    }
    if (tid < 16) {
      int gc = tid;
      int col = u0 + (gc & 3) + ((gc >> 2) << 9);
      s->wx1[gc]   = Wx1[col];
      s->bias1[gc] = bx1[col] + bh1[col];
      s->bias2[gc] = bx2[col] + bh2[col];
    }
    if (tid < 4) s->wl[tid] = Wl[u0 + tid];
    for (int i = tid; i < 4 * Bn; i += NTHR) { s->c1[i] = 0.f; s->c2[i] = 0.f; }
  }
  __syncthreads();

  // h1(0) from x(0), c1(-1)=0 ; zero our slice of g_h2[1] (h2(-1)=0)
  {
    int b = tid;
    float x0 = seq[b * Tn + 0];
    float hv[4];
#pragma unroll
    for (int u = 0; u < 4; ++u) {
      float zi = fmaf(x0, s->wx1[u],      s->bias1[u]);
      float zf = fmaf(x0, s->wx1[4 + u],  s->bias1[4 + u]);
      float zo = fmaf(x0, s->wx1[8 + u],  s->bias1[8 + u]);
      float zg = fmaf(x0, s->wx1[12 + u], s->bias1[12 + u]);
      float ii = sigf(zi), ff = sigf(zf), oo = sigf(zo), gg = tanhf(zg);
      (void)ff;
      float c = ii * gg;
      s->c1[u * Bn + b] = c;
      hv[u] = oo * tanhf(c);
    }
    float2* dst = g_h1[0] + b;
    dst[(2 * cta + 0) * Bn] = make_float2(hv[0], hv[1]);
    dst[(2 * cta + 1) * Bn] = make_float2(hv[2], hv[3]);
    for (int i = tid; i < 512; i += NTHR)
      g_h2[1][cta * 512 + i] = make_float2(0.f, 0.f);
  }
  grid_barrier();

  // ---------------- recurrence ----------------
  for (int t = 0; t < TPn; ++t) {
    const bool pred = (t >= Tn - 1);

    // deterministic output o(t-1) for main-phase steps (owner CTA, 2 batches)
    if (t >= 1 && t <= Tn - 1) {
      int ob = 2 * cta + (tid >> 7);
      int kq = tid & 127;
      const float2* col = g_h2[(t - 1) & 1] + ob;
      float2 hA = __ldcg(&col[(2 * kq) * Bn]);
      float2 hB = __ldcg(&col[(2 * kq + 1) * Bn]);
      float4 w  = reinterpret_cast<const float4*>(Wl)[kq];
      float p = hA.x * w.x + hA.y * w.y + hB.x * w.z + hB.y * w.w;
#pragma unroll
      for (int off = 16; off; off >>= 1) p += __shfl_xor_sync(0xffffffffu, p, off);
      if (lane == 0) s->red[warp] = p;
      __syncthreads();
      if (tid < 2) {
        float* r = s->red + tid * 4;
        g_out[(t - 1) * Bn + 2 * cta + tid] = r[0] + r[1] + r[2] + r[3];
      }
      __syncthreads();
    }

    float2 z1a[8][2], z2a[8][2];
#pragma unroll
    for (int i = 0; i < 8; ++i)
#pragma unroll
      for (int j = 0; j < 2; ++j) {
        z1a[i][j] = make_float2(0.f, 0.f);
        z2a[i][j] = make_float2(0.f, 0.f);
      }

    // z2 += h2(t-1) @ Wh2
    mat_pass<false>(s, g_h2[(t ^ 1) & 1], s->wh2, s->wh2, z2a, z1a, tid, bg, gcp);
    // z2 += h1(t) @ Wx2 ; z1 += h1(t) @ Wh1   (single staging pass)
    mat_pass<true>(s, g_h1[t & 1], s->wx2, s->wh1, z2a, z1a, tid, bg, gcp);

    // ---- combine layer 2 -> h2(t), publish ----
#pragma unroll
    for (int bb = 0; bb < 8; ++bb)
#pragma unroll
      for (int j = 0; j < 2; ++j) {
        int gc = 2 * gcp + j;
        s->zbuf[gc * ZP + b0 + bb] = z2a[bb][j].x + z2a[bb][j].y + s->bias2[gc];
      }
    __syncthreads();
    {
      int b = tid;
      float hv[4];
#pragma unroll
      for (int u = 0; u < 4; ++u) {
        float zi = s->zbuf[(u) * ZP + b];
        float zf = s->zbuf[(4 + u) * ZP + b];
        float zo = s->zbuf[(8 + u) * ZP + b];
        float zg = s->zbuf[(12 + u) * ZP + b];
        float ii = sigf(zi), ff = sigf(zf), oo = sigf(zo), gg = tanhf(zg);
        float c = ff * s->c2[u * Bn + b] + ii * gg;
        s->c2[u * Bn + b] = c;
        hv[u] = oo * tanhf(c);
      }
      float2* dst = g_h2[t & 1] + b;
      dst[(2 * cta + 0) * Bn] = make_float2(hv[0], hv[1]);
      dst[(2 * cta + 1) * Bn] = make_float2(hv[2], hv[3]);
    }
    __syncthreads();

    // ---- next-step input x(t+1) ----
    float xnext;
    if (!pred) {
      xnext = seq[tid * Tn + (t + 1)];
    } else {
      grid_barrier();  // h2(t) visible everywhere
      const float2* h2col = g_h2[t & 1] + tid;
      const float2* wl2 = reinterpret_cast<const float2*>(Wl);
      float o = 0.f;
      for (int k2 = 0; k2 < K2n; ++k2) {
        float2 hv = __ldcg(&h2col[k2 * Bn]);
        float2 wv = wl2[k2];
        o = fmaf(hv.x, wv.x, o);
        o = fmaf(hv.y, wv.y, o);
      }
      if (cta == 0) g_out[t * Bn + tid] = o;
      xnext = o + bl0;
    }

    // ---- combine layer 1 -> h1(t+1), publish ----
#pragma unroll
    for (int bb = 0; bb < 8; ++bb)
#pragma unroll
      for (int j = 0; j < 2; ++j) {
        int gc = 2 * gcp + j;
        s->zbuf[gc * ZP + b0 + bb] = z1a[bb][j].x + z1a[bb][j].y + s->bias1[gc];
      }
    __syncthreads();
    {
      int b = tid;
      float x = xnext;
      float hv[4];
#pragma unroll
      for (int u = 0; u < 4; ++u) {
        float zi = fmaf(x, s->wx1[u],      s->zbuf[(u) * ZP + b]);
        float zf = fmaf(x, s->wx1[4 + u],  s->zbuf[(4 + u) * ZP + b]);
        float zo = fmaf(x, s->wx1[8 + u],  s->zbuf[(8 + u) * ZP + b]);
        float zg = fmaf(x, s->wx1[12 + u], s->zbuf[(12 + u) * ZP + b]);
        float ii = sigf(zi), ff = sigf(zf), oo = sigf(zo), gg = tanhf(zg);
        float c = ff * s->c1[u * Bn + b] + ii * gg;
        s->c1[u * Bn + b] = c;
        hv[u] = oo * tanhf(c);
      }
      float2* dst = g_h1[(t + 1) & 1] + b;
      dst[(2 * cta + 0) * Bn] = make_float2(hv[0], hv[1]);
      dst[(2 * cta + 1) * Bn] = make_float2(hv[2], hv[3]);
    }
    grid_barrier();
  }

  // ---------------- output copy: out[b][tp] = o + bl ----------------
  for (int idx = cta * NTHR + tid; idx < TPn * Bn; idx += NCTA * NTHR) {
    int b = idx / TPn, tp = idx - b * TPn;
    out[idx] = __ldcg(&g_out[tp * Bn + b]) + bl0;
  }
}

extern "C" void kernel_launch(void* const* d_in, const int* in_sizes, int n_in,
                              void* d_out, int out_size) {
  (void)in_sizes; (void)n_in; (void)out_size;
  const float* seq = (const float*)d_in[0];
  // d_in[1] = predict (int scalar, fixed at 32)
  const float* Wx1 = (const float*)d_in[2];
  const float* bx1 = (const float*)d_in[3];
  const float* Wh1 = (const float*)d_in[4];
  const float* bh1 = (const float*)d_in[5];
  const float* Wx2 = (const float*)d_in[6];
  const float* bx2 = (const float*)d_in[7];
  const float* Wh2 = (const float*)d_in[8];
  const float* bh2 = (const float*)d_in[9];
  const float* Wl  = (const float*)d_in[10];
  const float* bl  = (const float*)d_in[11];

  cudaFuncSetAttribute(sine_rnn_kernel,
                       cudaFuncAttributeMaxDynamicSharedMemorySize,
                       (int)sizeof(Smem));
  sine_rnn_kernel<<<NCTA, NTHR, sizeof(Smem)>>>(
      seq, Wx1, bx1, Wh1, bh1, Wx2, bx2, Wh2, bh2, Wl, bl, (float*)d_out);
}